// round 12
// baseline (speedup 1.0000x reference)
#include <cuda_runtime.h>
#include <cuda_fp16.h>
#include <cstdint>

#define N_NODES 100000
#define N_EDGES 1600000
#define EN_TOT  (N_EDGES + N_NODES)   // edges + self loops
#define F_IN    512
#define H1      8
#define C1      8
#define D1      64                    // H1*C1
#define C2      40
#define C2P     48                    // padded h2 fp16 row (96B -> 16B-aligned float4s)

// ---------------- scratch (static device allocations; allowed) ----------------
__device__ float   g_h1 [N_NODES * D1];       // layer1 linear output fp32 [N,64]
__device__ __half2 g_h1h[N_NODES * (D1 / 2)]; // fp16 mirror for edge gather
__device__ float g_as1[N_NODES * H1];   // per-node src attention [N,8]
__device__ float g_ad1[N_NODES * H1];
__device__ float g_den1[N_NODES * H1];  // softmax denominators (accumulated in agg pass)
__device__ float g_out1[N_NODES * D1];  // layer1 UNNORMALIZED aggregate (fp32)
__device__ __half g_h2h[N_NODES * C2P]; // layer2 linear output, fp16 [N,48] (40 used)
__device__ float g_as2[N_NODES];
__device__ float g_ad2[N_NODES];
__device__ float g_den2[N_NODES];

__device__ __forceinline__ void red_add_v4(float* addr, float a, float b, float c, float d) {
    asm volatile("red.global.add.v4.f32 [%0], {%1,%2,%3,%4};"
                 :: "l"(addr), "f"(a), "f"(b), "f"(c), "f"(d) : "memory");
}
__device__ __forceinline__ void red_add_f(float* addr, float a) {
    asm volatile("red.global.add.f32 [%0], %1;" :: "l"(addr), "f"(a) : "memory");
}
__device__ __forceinline__ float lrelu(float e) { return e > 0.f ? e : 0.2f * e; }

__device__ __forceinline__ float to_tf32(float x) {
    uint32_t r;
    asm("cvt.rna.tf32.f32 %0, %1;" : "=r"(r) : "f"(x));
    return __uint_as_float(r);
}

// edge_index is int32 on device.
__device__ __forceinline__ void edge_sd(const int* __restrict__ ei, int i, int& s, int& d) {
    if (i < N_EDGES) { s = __ldg(&ei[i]); d = __ldg(&ei[N_EDGES + i]); }
    else             { s = d = i - N_EDGES; }
}

// =============================================================================
// GEMM1 (tf32 tensor-core): h1 = x @ W1 -> stored fp32 AND fp16 mirror.
// =============================================================================
#define BM 128
#define BN 64
#define BK 32
__global__ __launch_bounds__(256) void k_gemm1(const float* __restrict__ X,
                                               const float* __restrict__ W) {
    __shared__ float As[BK][BM + 8];   // [k][m], row stride 136 floats
    __shared__ float Bs[BK][BN + 8];   // [k][n], row stride 72 floats

    const int tid  = threadIdx.x;
    const int wid  = tid >> 5;
    const int lane = tid & 31;
    const int wm   = wid & 3;          // 0..3 : 32-row slab
    const int wn   = wid >> 2;         // 0..1 : 32-col slab
    const int lr   = lane >> 2;        // 0..7
    const int lc   = lane & 3;         // 0..3
    const int row0 = blockIdx.x * BM;

    float acc[2][4][4] = {};

    for (int k0 = 0; k0 < F_IN; k0 += BK) {
#pragma unroll
        for (int i = 0; i < 4; i++) {
            int fid = tid + i * 256;
            int r = fid >> 3;               // 0..127
            int c4 = fid & 7;               // 0..7
            int gr = row0 + r;
            if (gr >= N_NODES) gr = N_NODES - 1;
            float4 v = *(const float4*)&X[(size_t)gr * F_IN + k0 + c4 * 4];
            As[c4 * 4 + 0][r] = to_tf32(v.x);
            As[c4 * 4 + 1][r] = to_tf32(v.y);
            As[c4 * 4 + 2][r] = to_tf32(v.z);
            As[c4 * 4 + 3][r] = to_tf32(v.w);
        }
#pragma unroll
        for (int i = 0; i < 2; i++) {
            int fid = tid + i * 256;
            int r = fid >> 4;               // 0..31
            int c4 = fid & 15;              // 0..15
            float4 v = *(const float4*)&W[(k0 + r) * BN + c4 * 4];
            float4 t = make_float4(to_tf32(v.x), to_tf32(v.y), to_tf32(v.z), to_tf32(v.w));
            *(float4*)&Bs[r][c4 * 4] = t;
        }
        __syncthreads();

#pragma unroll
        for (int kk = 0; kk < BK; kk += 8) {
            uint32_t a[2][4], b[4][2];
#pragma unroll
            for (int mt = 0; mt < 2; mt++) {
                int m0 = wm * 32 + mt * 16;
                a[mt][0] = __float_as_uint(As[kk + lc    ][m0 + lr    ]);
                a[mt][1] = __float_as_uint(As[kk + lc    ][m0 + lr + 8]);
                a[mt][2] = __float_as_uint(As[kk + lc + 4][m0 + lr    ]);
                a[mt][3] = __float_as_uint(As[kk + lc + 4][m0 + lr + 8]);
            }
#pragma unroll
            for (int nt = 0; nt < 4; nt++) {
                int n0 = wn * 32 + nt * 8;
                b[nt][0] = __float_as_uint(Bs[kk + lc    ][n0 + lr]);
                b[nt][1] = __float_as_uint(Bs[kk + lc + 4][n0 + lr]);
            }
#pragma unroll
            for (int mt = 0; mt < 2; mt++)
#pragma unroll
                for (int nt = 0; nt < 4; nt++) {
                    asm volatile(
                        "mma.sync.aligned.m16n8k8.row.col.f32.tf32.tf32.f32 "
                        "{%0,%1,%2,%3}, {%4,%5,%6,%7}, {%8,%9}, {%0,%1,%2,%3};"
                        : "+f"(acc[mt][nt][0]), "+f"(acc[mt][nt][1]),
                          "+f"(acc[mt][nt][2]), "+f"(acc[mt][nt][3])
                        : "r"(a[mt][0]), "r"(a[mt][1]), "r"(a[mt][2]), "r"(a[mt][3]),
                          "r"(b[nt][0]), "r"(b[nt][1]));
                }
        }
        __syncthreads();
    }

    // Epilogue: fp32 float2 stores + fp16 mirror store.
#pragma unroll
    for (int mt = 0; mt < 2; mt++) {
#pragma unroll
        for (int nt = 0; nt < 4; nt++) {
            int r0 = row0 + wm * 32 + mt * 16 + lr;
            int c0 = wn * 32 + nt * 8 + 2 * lc;
            if (r0 < N_NODES) {
                *(float2*)&g_h1[(size_t)r0 * D1 + c0] =
                    make_float2(acc[mt][nt][0], acc[mt][nt][1]);
                g_h1h[(size_t)r0 * 32 + (c0 >> 1)] =
                    __floats2half2_rn(acc[mt][nt][0], acc[mt][nt][1]);
            }
            if (r0 + 8 < N_NODES) {
                *(float2*)&g_h1[(size_t)(r0 + 8) * D1 + c0] =
                    make_float2(acc[mt][nt][2], acc[mt][nt][3]);
                g_h1h[(size_t)(r0 + 8) * 32 + (c0 >> 1)] =
                    __floats2half2_rn(acc[mt][nt][2], acc[mt][nt][3]);
            }
        }
    }
}

// =============================================================================
// att1: per (node,head) attention scalars (reads fp32 h1 — full precision)
// =============================================================================
__global__ void k_att1(const float* __restrict__ att_src, const float* __restrict__ att_dst) {
    int idx = blockIdx.x * blockDim.x + threadIdx.x;
    if (idx >= N_NODES * H1) return;
    int h = idx & 7, n = idx >> 3;
    const float4* hp = (const float4*)&g_h1[(size_t)n * D1 + h * C1];
    float4 h0 = hp[0], h1v = hp[1];
    const float4* sp = (const float4*)&att_src[h * C1];
    const float4* dp = (const float4*)&att_dst[h * C1];
    float4 s0 = sp[0], s1 = sp[1], d0 = dp[0], d1 = dp[1];
    g_as1[idx] = h0.x * s0.x + h0.y * s0.y + h0.z * s0.z + h0.w * s0.w
               + h1v.x * s1.x + h1v.y * s1.y + h1v.z * s1.z + h1v.w * s1.w;
    g_ad1[idx] = h0.x * d0.x + h0.y * d0.y + h0.z * d0.z + h0.w * d0.w
               + h1v.x * d1.x + h1v.y * d1.y + h1v.z * d1.z + h1v.w * d1.w;
}

// =============================================================================
// FUSED edge pass layer1: out1[d] += w*h1[s]; den1[d] += w.
// 8 lanes per edge, lane == head.  fp16 gather (16B/lane), fp32 atomics.
// =============================================================================
__global__ void k_edge_agg1(const int* __restrict__ ei) {
    int t = blockIdx.x * blockDim.x + threadIdx.x;
    int e = t >> 3, l = t & 7;
    if (e >= EN_TOT) return;
    int s, d; edge_sd(ei, e, s, d);
    float w = __expf(lrelu(g_as1[s * H1 + l] + g_ad1[d * H1 + l]));
    float4 raw = *(const float4*)&g_h1h[(size_t)s * 32 + l * 4];   // 8 halfs
    __half2 p0 = *(__half2*)&raw.x, p1 = *(__half2*)&raw.y;
    __half2 p2 = *(__half2*)&raw.z, p3 = *(__half2*)&raw.w;
    float2 f0 = __half22float2(p0), f1 = __half22float2(p1);
    float2 f2 = __half22float2(p2), f3 = __half22float2(p3);
    float* op = &g_out1[(size_t)d * D1 + l * C1];
    red_add_v4(op,     f0.x * w, f0.y * w, f1.x * w, f1.y * w);
    red_add_v4(op + 4, f2.x * w, f2.y * w, f3.x * w, f3.y * w);
    red_add_f(&g_den1[d * H1 + l], w);
}

// =============================================================================
// layer2 prep (register-blocked tiled GEMM):
//   v = relu(out1/den1 + b1);  h2 = v @ W2 -> stored fp16 [N,48 padded];
//   as2/ad2 from fp32 accumulators (exact).
// =============================================================================
#define L2BM 128
__global__ __launch_bounds__(256) void k_l2prep(const float* __restrict__ b1,
                                                const float* __restrict__ W2,
                                                const float* __restrict__ att_src2,
                                                const float* __restrict__ att_dst2) {
    __shared__ float As[D1][L2BM + 4];
    __shared__ float Bs[D1][C2];
    __shared__ float b1s[D1];
    __shared__ float s2s[C2];
    __shared__ float d2s[C2];

    const int tid = threadIdx.x;
    const int row0 = blockIdx.x * L2BM;

    for (int i = tid; i < D1 * C2; i += 256) Bs[i / C2][i % C2] = W2[i];
    if (tid < D1) b1s[tid] = b1[tid];
    if (tid >= 64 && tid < 64 + C2) s2s[tid - 64] = att_src2[tid - 64];
    if (tid >= 128 && tid < 128 + C2) d2s[tid - 128] = att_dst2[tid - 128];
    __syncthreads();

#pragma unroll
    for (int i = 0; i < 8; i++) {
        int fid = tid + i * 256;
        int r = fid >> 4;
        int c4 = fid & 15;
        int gr = row0 + r;
        if (gr >= N_NODES) gr = N_NODES - 1;
        float q = 1.f / (g_den1[gr * H1 + (c4 >> 1)] + 1e-16f);
        float4 v = *(const float4*)&g_out1[(size_t)gr * D1 + c4 * 4];
        float e0 = v.x * q + b1s[c4 * 4 + 0];
        float e1 = v.y * q + b1s[c4 * 4 + 1];
        float e2 = v.z * q + b1s[c4 * 4 + 2];
        float e3 = v.w * q + b1s[c4 * 4 + 3];
        As[c4 * 4 + 0][r] = e0 > 0.f ? e0 : 0.f;
        As[c4 * 4 + 1][r] = e1 > 0.f ? e1 : 0.f;
        As[c4 * 4 + 2][r] = e2 > 0.f ? e2 : 0.f;
        As[c4 * 4 + 3][r] = e3 > 0.f ? e3 : 0.f;
    }
    __syncthreads();

    const int ty = tid >> 3;
    const int tx = tid & 7;
    float acc[4][5] = {};

#pragma unroll
    for (int k = 0; k < D1; k++) {
        float4 av = *(const float4*)&As[k][ty * 4];
        float a[4] = {av.x, av.y, av.z, av.w};
        float b[5];
#pragma unroll
        for (int j = 0; j < 5; j++) b[j] = Bs[k][tx * 5 + j];
#pragma unroll
        for (int i = 0; i < 4; i++)
#pragma unroll
            for (int j = 0; j < 5; j++) acc[i][j] += a[i] * b[j];
    }

#pragma unroll
    for (int i = 0; i < 4; i++) {
        int gr = row0 + ty * 4 + i;
        float ps = 0.f, pd = 0.f;
#pragma unroll
        for (int j = 0; j < 5; j++) {
            ps += acc[i][j] * s2s[tx * 5 + j];
            pd += acc[i][j] * d2s[tx * 5 + j];
        }
#pragma unroll
        for (int o = 4; o; o >>= 1) {
            ps += __shfl_xor_sync(0xffffffffu, ps, o);
            pd += __shfl_xor_sync(0xffffffffu, pd, o);
        }
        if (gr < N_NODES) {
#pragma unroll
            for (int j = 0; j < 5; j++)
                g_h2h[(size_t)gr * C2P + tx * 5 + j] = __float2half_rn(acc[i][j]);
            if (tx == 0) { g_as2[gr] = ps; g_ad2[gr] = pd; }
        }
    }
}

// =============================================================================
// FUSED edge pass layer2: out[d] += w*h2[s]; den2[d] += w.
// fp16 gather, 16B granules: lanes 0-4 each load float4 (8 halfs) covering the
// 80B row, issue 2 red.v4; lane 7 handles den.  out row stride 160B (16B-aln).
// =============================================================================
__global__ void k_edge_agg2(const int* __restrict__ ei, float* __restrict__ out) {
    int t = blockIdx.x * blockDim.x + threadIdx.x;
    int e = t >> 3, l = t & 7;
    if (e >= EN_TOT) return;
    int s, d; edge_sd(ei, e, s, d);
    float w = __expf(lrelu(g_as2[s] + g_ad2[d]));
    if (l < 5) {
        float4 raw = *(const float4*)&g_h2h[(size_t)s * C2P + l * 8];  // 8 halfs, 16B aligned
        __half2 p0 = *(__half2*)&raw.x, p1 = *(__half2*)&raw.y;
        __half2 p2 = *(__half2*)&raw.z, p3 = *(__half2*)&raw.w;
        float2 f0 = __half22float2(p0), f1 = __half22float2(p1);
        float2 f2 = __half22float2(p2), f3 = __half22float2(p3);
        float* op = &out[(size_t)d * C2 + l * 8];
        red_add_v4(op,     f0.x * w, f0.y * w, f1.x * w, f1.y * w);
        red_add_v4(op + 4, f2.x * w, f2.y * w, f3.x * w, f3.y * w);
    }
    if (l == 7) red_add_f(&g_den2[d], w);
}

// =============================================================================
// finalize: out = log_softmax(out/den2 + b2) per node (warp/node)
// =============================================================================
__global__ __launch_bounds__(256) void k_final(float* __restrict__ out,
                                               const float* __restrict__ b2) {
    const int w = threadIdx.x >> 5;
    const int lane = threadIdx.x & 31;
    const int n = blockIdx.x * 8 + w;
    if (n >= N_NODES) return;
    float* row = &out[(size_t)n * C2];
    float q = 1.f / (g_den2[n] + 1e-16f);
    float x0 = row[lane] * q + b2[lane];
    float x1 = (lane < 8) ? row[32 + lane] * q + b2[32 + lane] : -1e30f;
    float m = fmaxf(x0, x1);
#pragma unroll
    for (int o = 16; o; o >>= 1) m = fmaxf(m, __shfl_xor_sync(0xffffffffu, m, o));
    float s = expf(x0 - m) + ((lane < 8) ? expf(x1 - m) : 0.f);
#pragma unroll
    for (int o = 16; o; o >>= 1) s += __shfl_xor_sync(0xffffffffu, s, o);
    float l = m + logf(s);
    row[lane] = x0 - l;
    if (lane < 8) row[32 + lane] = x1 - l;
}

// =============================================================================
extern "C" void kernel_launch(void* const* d_in, const int* in_sizes, int n_in,
                              void* d_out, int out_size) {
    const float* x        = (const float*)d_in[0];
    const int*   ei       = (const int*)d_in[1];
    const float* W1       = (const float*)d_in[2];
    const float* att_src1 = (const float*)d_in[3];
    const float* att_dst1 = (const float*)d_in[4];
    const float* b1       = (const float*)d_in[5];
    const float* W2       = (const float*)d_in[6];
    const float* att_src2 = (const float*)d_in[7];
    const float* att_dst2 = (const float*)d_in[8];
    const float* b2       = (const float*)d_in[9];
    float*       out      = (float*)d_out;
    (void)in_sizes; (void)n_in;

    void *p_den1, *p_out1, *p_den2;
    cudaGetSymbolAddress(&p_den1, g_den1);
    cudaGetSymbolAddress(&p_out1, g_out1);
    cudaGetSymbolAddress(&p_den2, g_den2);

    cudaMemsetAsync(p_den1, 0, (size_t)N_NODES * H1 * sizeof(float));
    cudaMemsetAsync(p_out1, 0, (size_t)N_NODES * D1 * sizeof(float));
    cudaMemsetAsync(p_den2, 0, (size_t)N_NODES * sizeof(float));
    cudaMemsetAsync(out,    0, (size_t)out_size * sizeof(float));

    const int TB = 256;
    k_gemm1<<<(N_NODES + BM - 1) / BM, TB>>>(x, W1);
    k_att1<<<(N_NODES * H1 + TB - 1) / TB, TB>>>(att_src1, att_dst1);
    k_edge_agg1<<<((EN_TOT * 8) + TB - 1) / TB, TB>>>(ei);
    k_l2prep<<<(N_NODES + L2BM - 1) / L2BM, TB>>>(b1, W2, att_src2, att_dst2);
    k_edge_agg2<<<((EN_TOT * 8) + TB - 1) / TB, TB>>>(ei, out);
    k_final<<<(N_NODES + 7) / 8, TB>>>(out, b2);
}

// round 13
// speedup vs baseline: 1.3384x; 1.3384x over previous
#include <cuda_runtime.h>
#include <cuda_fp16.h>
#include <cstdint>

#define N_NODES 100000
#define N_EDGES 1600000
#define EN_TOT  (N_EDGES + N_NODES)   // edges + self loops
#define F_IN    512
#define H1      8
#define C1      8
#define D1      64                    // H1*C1
#define C2      40
#define C2P     48                    // padded h2 fp16 row (96B, 16B-aligned float4s)
#define NBLK    ((N_NODES + 1023) / 1024)   // 98 scan blocks

// ---------------- scratch (static device allocations; allowed) ----------------
__device__ float   g_h1 [N_NODES * D1];       // layer1 linear output fp32 [N,64]
__device__ __half2 g_h1h[N_NODES * (D1 / 2)]; // fp16 mirror for edge gather
__device__ float g_as1[N_NODES * H1];
__device__ float g_ad1[N_NODES * H1];
__device__ float g_den1[N_NODES * H1];
__device__ float g_out1[N_NODES * D1];
__device__ __half g_h2h[N_NODES * C2P];
__device__ float g_as2[N_NODES];
__device__ float g_ad2[N_NODES];
__device__ float g_den2[N_NODES];
// CSR scratch
__device__ int g_cnt [N_NODES];
__device__ int g_cnt2[N_NODES];
__device__ int g_start[N_NODES + 1];
__device__ int g_blksum[NBLK];
__device__ int g_blkoff[NBLK];
__device__ int g_csr[EN_TOT];

__device__ __forceinline__ float lrelu(float e) { return e > 0.f ? e : 0.2f * e; }

__device__ __forceinline__ float to_tf32(float x) {
    uint32_t r;
    asm("cvt.rna.tf32.f32 %0, %1;" : "=r"(r) : "f"(x));
    return __uint_as_float(r);
}

// edge_index is int32 on device.
__device__ __forceinline__ void edge_sd(const int* __restrict__ ei, int i, int& s, int& d) {
    if (i < N_EDGES) { s = __ldg(&ei[i]); d = __ldg(&ei[N_EDGES + i]); }
    else             { s = d = i - N_EDGES; }
}

// =============================================================================
// CSR build: count -> scan (3 kernels) -> fill
// =============================================================================
__global__ void k_count(const int* __restrict__ ei) {
    int i = blockIdx.x * blockDim.x + threadIdx.x;
    if (i >= EN_TOT) return;
    int s, d; edge_sd(ei, i, s, d);
    atomicAdd(&g_cnt[d], 1);
}

__global__ __launch_bounds__(1024) void k_scanA() {
    __shared__ int sm[1024];
    int t = blockIdx.x * 1024 + threadIdx.x;
    int v = (t < N_NODES) ? g_cnt[t] : 0;
    sm[threadIdx.x] = v;
    __syncthreads();
#pragma unroll
    for (int off = 1; off < 1024; off <<= 1) {
        int x = (threadIdx.x >= off) ? sm[threadIdx.x - off] : 0;
        __syncthreads();
        sm[threadIdx.x] += x;
        __syncthreads();
    }
    if (t < N_NODES) g_start[t] = sm[threadIdx.x] - v;       // exclusive within block
    if (threadIdx.x == 1023) g_blksum[blockIdx.x] = sm[1023];
}

__global__ void k_scanB() {          // 1 block, 128 threads, NBLK<=128
    __shared__ int sm[128];
    int t = threadIdx.x;
    int v = (t < NBLK) ? g_blksum[t] : 0;
    sm[t] = v;
    __syncthreads();
#pragma unroll
    for (int off = 1; off < 128; off <<= 1) {
        int x = (t >= off) ? sm[t - off] : 0;
        __syncthreads();
        sm[t] += x;
        __syncthreads();
    }
    if (t < NBLK) g_blkoff[t] = sm[t] - v;
}

__global__ __launch_bounds__(1024) void k_scanC() {
    int t = blockIdx.x * 1024 + threadIdx.x;
    if (t < N_NODES) g_start[t] += g_blkoff[blockIdx.x];
    if (t == 0) g_start[N_NODES] = EN_TOT;
}

__global__ void k_fill(const int* __restrict__ ei) {
    int i = blockIdx.x * blockDim.x + threadIdx.x;
    if (i >= EN_TOT) return;
    int s, d; edge_sd(ei, i, s, d);
    int pos = atomicAdd(&g_cnt2[d], 1);
    g_csr[g_start[d] + pos] = s;
}

// =============================================================================
// GEMM1 (tf32 tensor-core): h1 = x @ W1 -> stored fp32 AND fp16 mirror.
// =============================================================================
#define BM 128
#define BN 64
#define BK 32
__global__ __launch_bounds__(256) void k_gemm1(const float* __restrict__ X,
                                               const float* __restrict__ W) {
    __shared__ float As[BK][BM + 8];
    __shared__ float Bs[BK][BN + 8];

    const int tid  = threadIdx.x;
    const int wid  = tid >> 5;
    const int lane = tid & 31;
    const int wm   = wid & 3;
    const int wn   = wid >> 2;
    const int lr   = lane >> 2;
    const int lc   = lane & 3;
    const int row0 = blockIdx.x * BM;

    float acc[2][4][4] = {};

    for (int k0 = 0; k0 < F_IN; k0 += BK) {
#pragma unroll
        for (int i = 0; i < 4; i++) {
            int fid = tid + i * 256;
            int r = fid >> 3;
            int c4 = fid & 7;
            int gr = row0 + r;
            if (gr >= N_NODES) gr = N_NODES - 1;
            float4 v = *(const float4*)&X[(size_t)gr * F_IN + k0 + c4 * 4];
            As[c4 * 4 + 0][r] = to_tf32(v.x);
            As[c4 * 4 + 1][r] = to_tf32(v.y);
            As[c4 * 4 + 2][r] = to_tf32(v.z);
            As[c4 * 4 + 3][r] = to_tf32(v.w);
        }
#pragma unroll
        for (int i = 0; i < 2; i++) {
            int fid = tid + i * 256;
            int r = fid >> 4;
            int c4 = fid & 15;
            float4 v = *(const float4*)&W[(k0 + r) * BN + c4 * 4];
            float4 t = make_float4(to_tf32(v.x), to_tf32(v.y), to_tf32(v.z), to_tf32(v.w));
            *(float4*)&Bs[r][c4 * 4] = t;
        }
        __syncthreads();

#pragma unroll
        for (int kk = 0; kk < BK; kk += 8) {
            uint32_t a[2][4], b[4][2];
#pragma unroll
            for (int mt = 0; mt < 2; mt++) {
                int m0 = wm * 32 + mt * 16;
                a[mt][0] = __float_as_uint(As[kk + lc    ][m0 + lr    ]);
                a[mt][1] = __float_as_uint(As[kk + lc    ][m0 + lr + 8]);
                a[mt][2] = __float_as_uint(As[kk + lc + 4][m0 + lr    ]);
                a[mt][3] = __float_as_uint(As[kk + lc + 4][m0 + lr + 8]);
            }
#pragma unroll
            for (int nt = 0; nt < 4; nt++) {
                int n0 = wn * 32 + nt * 8;
                b[nt][0] = __float_as_uint(Bs[kk + lc    ][n0 + lr]);
                b[nt][1] = __float_as_uint(Bs[kk + lc + 4][n0 + lr]);
            }
#pragma unroll
            for (int mt = 0; mt < 2; mt++)
#pragma unroll
                for (int nt = 0; nt < 4; nt++) {
                    asm volatile(
                        "mma.sync.aligned.m16n8k8.row.col.f32.tf32.tf32.f32 "
                        "{%0,%1,%2,%3}, {%4,%5,%6,%7}, {%8,%9}, {%0,%1,%2,%3};"
                        : "+f"(acc[mt][nt][0]), "+f"(acc[mt][nt][1]),
                          "+f"(acc[mt][nt][2]), "+f"(acc[mt][nt][3])
                        : "r"(a[mt][0]), "r"(a[mt][1]), "r"(a[mt][2]), "r"(a[mt][3]),
                          "r"(b[nt][0]), "r"(b[nt][1]));
                }
        }
        __syncthreads();
    }

#pragma unroll
    for (int mt = 0; mt < 2; mt++) {
#pragma unroll
        for (int nt = 0; nt < 4; nt++) {
            int r0 = row0 + wm * 32 + mt * 16 + lr;
            int c0 = wn * 32 + nt * 8 + 2 * lc;
            if (r0 < N_NODES) {
                *(float2*)&g_h1[(size_t)r0 * D1 + c0] =
                    make_float2(acc[mt][nt][0], acc[mt][nt][1]);
                g_h1h[(size_t)r0 * 32 + (c0 >> 1)] =
                    __floats2half2_rn(acc[mt][nt][0], acc[mt][nt][1]);
            }
            if (r0 + 8 < N_NODES) {
                *(float2*)&g_h1[(size_t)(r0 + 8) * D1 + c0] =
                    make_float2(acc[mt][nt][2], acc[mt][nt][3]);
                g_h1h[(size_t)(r0 + 8) * 32 + (c0 >> 1)] =
                    __floats2half2_rn(acc[mt][nt][2], acc[mt][nt][3]);
            }
        }
    }
}

// =============================================================================
// att1: per (node,head) attention scalars (fp32 h1 — full precision)
// =============================================================================
__global__ void k_att1(const float* __restrict__ att_src, const float* __restrict__ att_dst) {
    int idx = blockIdx.x * blockDim.x + threadIdx.x;
    if (idx >= N_NODES * H1) return;
    int h = idx & 7, n = idx >> 3;
    const float4* hp = (const float4*)&g_h1[(size_t)n * D1 + h * C1];
    float4 h0 = hp[0], h1v = hp[1];
    const float4* sp = (const float4*)&att_src[h * C1];
    const float4* dp = (const float4*)&att_dst[h * C1];
    float4 s0 = sp[0], s1 = sp[1], d0 = dp[0], d1 = dp[1];
    g_as1[idx] = h0.x * s0.x + h0.y * s0.y + h0.z * s0.z + h0.w * s0.w
               + h1v.x * s1.x + h1v.y * s1.y + h1v.z * s1.z + h1v.w * s1.w;
    g_ad1[idx] = h0.x * d0.x + h0.y * d0.y + h0.z * d0.z + h0.w * d0.w
               + h1v.x * d1.x + h1v.y * d1.y + h1v.z * d1.z + h1v.w * d1.w;
}

// =============================================================================
// CSR edge pass layer1: warp per dst. 32 lanes = 4 edge-slots x 8 heads.
// Register accumulation, shuffle reduce, ONE coalesced 256B store. No atomics.
// =============================================================================
__global__ __launch_bounds__(256) void k_agg1_csr() {
    int gw = (blockIdx.x * 256 + threadIdx.x) >> 5;   // dst node
    if (gw >= N_NODES) return;
    const int d    = gw;
    const int lane = threadIdx.x & 31;
    const int es   = lane >> 3;                        // edge slot 0..3
    const int l    = lane & 7;                         // head
    const int e0 = g_start[d], e1 = g_start[d + 1];

    const float ad = g_ad1[d * H1 + l];
    float acc[8] = {};
    float den = 0.f;

    for (int e = e0 + es; e < e1; e += 4) {
        int s = g_csr[e];
        float w = __expf(lrelu(g_as1[s * H1 + l] + ad));
        float4 raw = *(const float4*)&g_h1h[(size_t)s * 32 + l * 4];  // 8 halfs
        __half2 p0 = *(__half2*)&raw.x, p1 = *(__half2*)&raw.y;
        __half2 p2 = *(__half2*)&raw.z, p3 = *(__half2*)&raw.w;
        float2 f0 = __half22float2(p0), f1 = __half22float2(p1);
        float2 f2 = __half22float2(p2), f3 = __half22float2(p3);
        acc[0] += w * f0.x; acc[1] += w * f0.y;
        acc[2] += w * f1.x; acc[3] += w * f1.y;
        acc[4] += w * f2.x; acc[5] += w * f2.y;
        acc[6] += w * f3.x; acc[7] += w * f3.y;
        den += w;
    }
    __syncwarp();
#pragma unroll
    for (int off = 8; off <= 16; off <<= 1) {
#pragma unroll
        for (int k = 0; k < 8; k++) acc[k] += __shfl_xor_sync(0xffffffffu, acc[k], off);
        den += __shfl_xor_sync(0xffffffffu, den, off);
    }
    if (es == 0) {
        float* op = &g_out1[(size_t)d * D1 + l * C1];
        *(float4*)op       = make_float4(acc[0], acc[1], acc[2], acc[3]);
        *(float4*)(op + 4) = make_float4(acc[4], acc[5], acc[6], acc[7]);
        g_den1[d * H1 + l] = den;
    }
}

// =============================================================================
// layer2 prep (register-blocked tiled GEMM):
//   v = relu(out1/den1 + b1);  h2 = v @ W2 -> fp16 [N,48];  as2/ad2 fp32.
// =============================================================================
#define L2BM 128
__global__ __launch_bounds__(256) void k_l2prep(const float* __restrict__ b1,
                                                const float* __restrict__ W2,
                                                const float* __restrict__ att_src2,
                                                const float* __restrict__ att_dst2) {
    __shared__ float As[D1][L2BM + 4];
    __shared__ float Bs[D1][C2];
    __shared__ float b1s[D1];
    __shared__ float s2s[C2];
    __shared__ float d2s[C2];

    const int tid = threadIdx.x;
    const int row0 = blockIdx.x * L2BM;

    for (int i = tid; i < D1 * C2; i += 256) Bs[i / C2][i % C2] = W2[i];
    if (tid < D1) b1s[tid] = b1[tid];
    if (tid >= 64 && tid < 64 + C2) s2s[tid - 64] = att_src2[tid - 64];
    if (tid >= 128 && tid < 128 + C2) d2s[tid - 128] = att_dst2[tid - 128];
    __syncthreads();

#pragma unroll
    for (int i = 0; i < 8; i++) {
        int fid = tid + i * 256;
        int r = fid >> 4;
        int c4 = fid & 15;
        int gr = row0 + r;
        if (gr >= N_NODES) gr = N_NODES - 1;
        float q = 1.f / (g_den1[gr * H1 + (c4 >> 1)] + 1e-16f);
        float4 v = *(const float4*)&g_out1[(size_t)gr * D1 + c4 * 4];
        float e0 = v.x * q + b1s[c4 * 4 + 0];
        float e1 = v.y * q + b1s[c4 * 4 + 1];
        float e2 = v.z * q + b1s[c4 * 4 + 2];
        float e3 = v.w * q + b1s[c4 * 4 + 3];
        As[c4 * 4 + 0][r] = e0 > 0.f ? e0 : 0.f;
        As[c4 * 4 + 1][r] = e1 > 0.f ? e1 : 0.f;
        As[c4 * 4 + 2][r] = e2 > 0.f ? e2 : 0.f;
        As[c4 * 4 + 3][r] = e3 > 0.f ? e3 : 0.f;
    }
    __syncthreads();

    const int ty = tid >> 3;
    const int tx = tid & 7;
    float acc[4][5] = {};

#pragma unroll
    for (int k = 0; k < D1; k++) {
        float4 av = *(const float4*)&As[k][ty * 4];
        float a[4] = {av.x, av.y, av.z, av.w};
        float b[5];
#pragma unroll
        for (int j = 0; j < 5; j++) b[j] = Bs[k][tx * 5 + j];
#pragma unroll
        for (int i = 0; i < 4; i++)
#pragma unroll
            for (int j = 0; j < 5; j++) acc[i][j] += a[i] * b[j];
    }

#pragma unroll
    for (int i = 0; i < 4; i++) {
        int gr = row0 + ty * 4 + i;
        float ps = 0.f, pd = 0.f;
#pragma unroll
        for (int j = 0; j < 5; j++) {
            ps += acc[i][j] * s2s[tx * 5 + j];
            pd += acc[i][j] * d2s[tx * 5 + j];
        }
#pragma unroll
        for (int o = 4; o; o >>= 1) {
            ps += __shfl_xor_sync(0xffffffffu, ps, o);
            pd += __shfl_xor_sync(0xffffffffu, pd, o);
        }
        if (gr < N_NODES) {
#pragma unroll
            for (int j = 0; j < 5; j++)
                g_h2h[(size_t)gr * C2P + tx * 5 + j] = __float2half_rn(acc[i][j]);
            if (tx == 0) { g_as2[gr] = ps; g_ad2[gr] = pd; }
        }
    }
}

// =============================================================================
// CSR edge pass layer2: warp per dst. Lanes l<5 carry 8 halfs each (80B row);
// lane 7 carries den. Register accumulation, ONE 160B store. No atomics.
// =============================================================================
__global__ __launch_bounds__(256) void k_agg2_csr(float* __restrict__ out) {
    int gw = (blockIdx.x * 256 + threadIdx.x) >> 5;
    if (gw >= N_NODES) return;
    const int d    = gw;
    const int lane = threadIdx.x & 31;
    const int es   = lane >> 3;
    const int l    = lane & 7;
    const int e0 = g_start[d], e1 = g_start[d + 1];

    const float ad = g_ad2[d];
    float acc[8] = {};
    float den = 0.f;

    for (int e = e0 + es; e < e1; e += 4) {
        int s = g_csr[e];
        float w = __expf(lrelu(g_as2[s] + ad));
        if (l < 5) {
            float4 raw = *(const float4*)&g_h2h[(size_t)s * C2P + l * 8];  // 8 halfs
            __half2 p0 = *(__half2*)&raw.x, p1 = *(__half2*)&raw.y;
            __half2 p2 = *(__half2*)&raw.z, p3 = *(__half2*)&raw.w;
            float2 f0 = __half22float2(p0), f1 = __half22float2(p1);
            float2 f2 = __half22float2(p2), f3 = __half22float2(p3);
            acc[0] += w * f0.x; acc[1] += w * f0.y;
            acc[2] += w * f1.x; acc[3] += w * f1.y;
            acc[4] += w * f2.x; acc[5] += w * f2.y;
            acc[6] += w * f3.x; acc[7] += w * f3.y;
        }
        den += w;
    }
    __syncwarp();
#pragma unroll
    for (int off = 8; off <= 16; off <<= 1) {
#pragma unroll
        for (int k = 0; k < 8; k++) acc[k] += __shfl_xor_sync(0xffffffffu, acc[k], off);
        den += __shfl_xor_sync(0xffffffffu, den, off);
    }
    if (es == 0) {
        if (l < 5) {
            float* op = &out[(size_t)d * C2 + l * 8];
            *(float4*)op       = make_float4(acc[0], acc[1], acc[2], acc[3]);
            *(float4*)(op + 4) = make_float4(acc[4], acc[5], acc[6], acc[7]);
        }
        if (l == 7) g_den2[d] = den;
    }
}

// =============================================================================
// finalize: out = log_softmax(out/den2 + b2) per node (warp/node)
// =============================================================================
__global__ __launch_bounds__(256) void k_final(float* __restrict__ out,
                                               const float* __restrict__ b2) {
    const int w = threadIdx.x >> 5;
    const int lane = threadIdx.x & 31;
    const int n = blockIdx.x * 8 + w;
    if (n >= N_NODES) return;
    float* row = &out[(size_t)n * C2];
    float q = 1.f / (g_den2[n] + 1e-16f);
    float x0 = row[lane] * q + b2[lane];
    float x1 = (lane < 8) ? row[32 + lane] * q + b2[32 + lane] : -1e30f;
    float m = fmaxf(x0, x1);
#pragma unroll
    for (int o = 16; o; o >>= 1) m = fmaxf(m, __shfl_xor_sync(0xffffffffu, m, o));
    float s = expf(x0 - m) + ((lane < 8) ? expf(x1 - m) : 0.f);
#pragma unroll
    for (int o = 16; o; o >>= 1) s += __shfl_xor_sync(0xffffffffu, s, o);
    float l = m + logf(s);
    row[lane] = x0 - l;
    if (lane < 8) row[32 + lane] = x1 - l;
}

// =============================================================================
extern "C" void kernel_launch(void* const* d_in, const int* in_sizes, int n_in,
                              void* d_out, int out_size) {
    const float* x        = (const float*)d_in[0];
    const int*   ei       = (const int*)d_in[1];
    const float* W1       = (const float*)d_in[2];
    const float* att_src1 = (const float*)d_in[3];
    const float* att_dst1 = (const float*)d_in[4];
    const float* b1       = (const float*)d_in[5];
    const float* W2       = (const float*)d_in[6];
    const float* att_src2 = (const float*)d_in[7];
    const float* att_dst2 = (const float*)d_in[8];
    const float* b2       = (const float*)d_in[9];
    float*       out      = (float*)d_out;
    (void)in_sizes; (void)n_in; (void)out_size;

    void *p_cnt, *p_cnt2;
    cudaGetSymbolAddress(&p_cnt,  g_cnt);
    cudaGetSymbolAddress(&p_cnt2, g_cnt2);
    cudaMemsetAsync(p_cnt,  0, (size_t)N_NODES * sizeof(int));
    cudaMemsetAsync(p_cnt2, 0, (size_t)N_NODES * sizeof(int));

    const int TB = 256;
    // CSR build
    k_count<<<(EN_TOT + TB - 1) / TB, TB>>>(ei);
    k_scanA<<<NBLK, 1024>>>();
    k_scanB<<<1, 128>>>();
    k_scanC<<<NBLK, 1024>>>();
    k_fill<<<(EN_TOT + TB - 1) / TB, TB>>>(ei);
    // GAT pipeline
    k_gemm1<<<(N_NODES + BM - 1) / BM, TB>>>(x, W1);
    k_att1<<<(N_NODES * H1 + TB - 1) / TB, TB>>>(att_src1, att_dst1);
    k_agg1_csr<<<(N_NODES * 32 + TB - 1) / TB, TB>>>();
    k_l2prep<<<(N_NODES + L2BM - 1) / L2BM, TB>>>(b1, W2, att_src2, att_dst2);
    k_agg2_csr<<<(N_NODES * 32 + TB - 1) / TB, TB>>>(out);
    k_final<<<(N_NODES + 7) / 8, TB>>>(out, b2);
}

// round 15
// speedup vs baseline: 1.3589x; 1.0153x over previous
#include <cuda_runtime.h>
#include <cuda_fp16.h>
#include <cstdint>

#define N_NODES 100000
#define N_EDGES 1600000
#define EN_TOT  (N_EDGES + N_NODES)   // edges + self loops
#define F_IN    512
#define H1      8
#define C1      8
#define D1      64                    // H1*C1
#define C2      40
#define C2P     48                    // padded h2 fp16 row (96B, 16B-aligned float4s)
#define NBLK    ((N_NODES + 1023) / 1024)   // 98 scan blocks

// ---------------- scratch (static device allocations; allowed) ----------------
__device__ float   g_h1 [N_NODES * D1];       // layer1 linear output fp32 [N,64]
__device__ __half2 g_h1h[N_NODES * (D1 / 2)]; // fp16 mirror for edge gather
__device__ float g_as1[N_NODES * H1];
__device__ float g_ad1[N_NODES * H1];
__device__ float g_den1[N_NODES * H1];
__device__ float g_out1[N_NODES * D1];
__device__ __half g_h2h[N_NODES * C2P];
__device__ float g_as2[N_NODES];
__device__ float g_ad2[N_NODES];
__device__ float g_den2[N_NODES];
// CSR scratch
__device__ int g_cnt [N_NODES];
__device__ int g_cnt2[N_NODES];
__device__ int g_start[N_NODES + 1];
__device__ int g_blksum[NBLK];
__device__ int g_blkoff[NBLK];
__device__ int g_csr[EN_TOT];

__device__ __forceinline__ float lrelu(float e) { return e > 0.f ? e : 0.2f * e; }

__device__ __forceinline__ float to_tf32(float x) {
    uint32_t r;
    asm("cvt.rna.tf32.f32 %0, %1;" : "=r"(r) : "f"(x));
    return __uint_as_float(r);
}

// edge_index is int32 on device.
__device__ __forceinline__ void edge_sd(const int* __restrict__ ei, int i, int& s, int& d) {
    if (i < N_EDGES) { s = __ldg(&ei[i]); d = __ldg(&ei[N_EDGES + i]); }
    else             { s = d = i - N_EDGES; }
}

// =============================================================================
// CSR build: count -> scan (3 kernels) -> fill
// =============================================================================
__global__ void k_count(const int* __restrict__ ei) {
    int i = blockIdx.x * blockDim.x + threadIdx.x;
    if (i >= EN_TOT) return;
    int d = (i < N_EDGES) ? __ldg(&ei[N_EDGES + i]) : i - N_EDGES;   // dst only
    atomicAdd(&g_cnt[d], 1);
}

__global__ __launch_bounds__(1024) void k_scanA() {
    __shared__ int sm[1024];
    int t = blockIdx.x * 1024 + threadIdx.x;
    int v = (t < N_NODES) ? g_cnt[t] : 0;
    sm[threadIdx.x] = v;
    __syncthreads();
#pragma unroll
    for (int off = 1; off < 1024; off <<= 1) {
        int x = (threadIdx.x >= off) ? sm[threadIdx.x - off] : 0;
        __syncthreads();
        sm[threadIdx.x] += x;
        __syncthreads();
    }
    if (t < N_NODES) g_start[t] = sm[threadIdx.x] - v;       // exclusive within block
    if (threadIdx.x == 1023) g_blksum[blockIdx.x] = sm[1023];
}

__global__ void k_scanB() {          // 1 block, 128 threads, NBLK<=128
    __shared__ int sm[128];
    int t = threadIdx.x;
    int v = (t < NBLK) ? g_blksum[t] : 0;
    sm[t] = v;
    __syncthreads();
#pragma unroll
    for (int off = 1; off < 128; off <<= 1) {
        int x = (t >= off) ? sm[t - off] : 0;
        __syncthreads();
        sm[t] += x;
        __syncthreads();
    }
    if (t < NBLK) g_blkoff[t] = sm[t] - v;
}

__global__ __launch_bounds__(1024) void k_scanC() {
    int t = blockIdx.x * 1024 + threadIdx.x;
    if (t < N_NODES) {
        g_start[t] += g_blkoff[blockIdx.x];
        g_cnt2[t] = 0;                    // fold cursor init here (no memset)
    }
    if (t == 0) g_start[N_NODES] = EN_TOT;
}

__global__ void k_fill(const int* __restrict__ ei) {
    int i = blockIdx.x * blockDim.x + threadIdx.x;
    if (i >= EN_TOT) return;
    int s, d; edge_sd(ei, i, s, d);
    int pos = atomicAdd(&g_cnt2[d], 1);
    g_csr[g_start[d] + pos] = s;
}

// =============================================================================
// GEMM1 (tf32 tensor-core): h1 = x @ W1 -> stored fp32 AND fp16 mirror.
// =============================================================================
#define BM 128
#define BN 64
#define BK 32
__global__ __launch_bounds__(256) void k_gemm1(const float* __restrict__ X,
                                               const float* __restrict__ W) {
    __shared__ float As[BK][BM + 8];
    __shared__ float Bs[BK][BN + 8];

    const int tid  = threadIdx.x;
    const int wid  = tid >> 5;
    const int lane = tid & 31;
    const int wm   = wid & 3;
    const int wn   = wid >> 2;
    const int lr   = lane >> 2;
    const int lc   = lane & 3;
    const int row0 = blockIdx.x * BM;

    float acc[2][4][4] = {};

    for (int k0 = 0; k0 < F_IN; k0 += BK) {
#pragma unroll
        for (int i = 0; i < 4; i++) {
            int fid = tid + i * 256;
            int r = fid >> 3;
            int c4 = fid & 7;
            int gr = row0 + r;
            if (gr >= N_NODES) gr = N_NODES - 1;
            float4 v = *(const float4*)&X[(size_t)gr * F_IN + k0 + c4 * 4];
            As[c4 * 4 + 0][r] = to_tf32(v.x);
            As[c4 * 4 + 1][r] = to_tf32(v.y);
            As[c4 * 4 + 2][r] = to_tf32(v.z);
            As[c4 * 4 + 3][r] = to_tf32(v.w);
        }
#pragma unroll
        for (int i = 0; i < 2; i++) {
            int fid = tid + i * 256;
            int r = fid >> 4;
            int c4 = fid & 15;
            float4 v = *(const float4*)&W[(k0 + r) * BN + c4 * 4];
            float4 t = make_float4(to_tf32(v.x), to_tf32(v.y), to_tf32(v.z), to_tf32(v.w));
            *(float4*)&Bs[r][c4 * 4] = t;
        }
        __syncthreads();

#pragma unroll
        for (int kk = 0; kk < BK; kk += 8) {
            uint32_t a[2][4], b[4][2];
#pragma unroll
            for (int mt = 0; mt < 2; mt++) {
                int m0 = wm * 32 + mt * 16;
                a[mt][0] = __float_as_uint(As[kk + lc    ][m0 + lr    ]);
                a[mt][1] = __float_as_uint(As[kk + lc    ][m0 + lr + 8]);
                a[mt][2] = __float_as_uint(As[kk + lc + 4][m0 + lr    ]);
                a[mt][3] = __float_as_uint(As[kk + lc + 4][m0 + lr + 8]);
            }
#pragma unroll
            for (int nt = 0; nt < 4; nt++) {
                int n0 = wn * 32 + nt * 8;
                b[nt][0] = __float_as_uint(Bs[kk + lc    ][n0 + lr]);
                b[nt][1] = __float_as_uint(Bs[kk + lc + 4][n0 + lr]);
            }
#pragma unroll
            for (int mt = 0; mt < 2; mt++)
#pragma unroll
                for (int nt = 0; nt < 4; nt++) {
                    asm volatile(
                        "mma.sync.aligned.m16n8k8.row.col.f32.tf32.tf32.f32 "
                        "{%0,%1,%2,%3}, {%4,%5,%6,%7}, {%8,%9}, {%0,%1,%2,%3};"
                        : "+f"(acc[mt][nt][0]), "+f"(acc[mt][nt][1]),
                          "+f"(acc[mt][nt][2]), "+f"(acc[mt][nt][3])
                        : "r"(a[mt][0]), "r"(a[mt][1]), "r"(a[mt][2]), "r"(a[mt][3]),
                          "r"(b[nt][0]), "r"(b[nt][1]));
                }
        }
        __syncthreads();
    }

#pragma unroll
    for (int mt = 0; mt < 2; mt++) {
#pragma unroll
        for (int nt = 0; nt < 4; nt++) {
            int r0 = row0 + wm * 32 + mt * 16 + lr;
            int c0 = wn * 32 + nt * 8 + 2 * lc;
            if (r0 < N_NODES) {
                *(float2*)&g_h1[(size_t)r0 * D1 + c0] =
                    make_float2(acc[mt][nt][0], acc[mt][nt][1]);
                g_h1h[(size_t)r0 * 32 + (c0 >> 1)] =
                    __floats2half2_rn(acc[mt][nt][0], acc[mt][nt][1]);
            }
            if (r0 + 8 < N_NODES) {
                *(float2*)&g_h1[(size_t)(r0 + 8) * D1 + c0] =
                    make_float2(acc[mt][nt][2], acc[mt][nt][3]);
                g_h1h[(size_t)(r0 + 8) * 32 + (c0 >> 1)] =
                    __floats2half2_rn(acc[mt][nt][2], acc[mt][nt][3]);
            }
        }
    }
}

// =============================================================================
// att1: per (node,head) attention scalars (fp32 h1 — full precision)
// =============================================================================
__global__ void k_att1(const float* __restrict__ att_src, const float* __restrict__ att_dst) {
    int idx = blockIdx.x * blockDim.x + threadIdx.x;
    if (idx >= N_NODES * H1) return;
    int h = idx & 7, n = idx >> 3;
    const float4* hp = (const float4*)&g_h1[(size_t)n * D1 + h * C1];
    float4 h0 = hp[0], h1v = hp[1];
    const float4* sp = (const float4*)&att_src[h * C1];
    const float4* dp = (const float4*)&att_dst[h * C1];
    float4 s0 = sp[0], s1 = sp[1], d0 = dp[0], d1 = dp[1];
    g_as1[idx] = h0.x * s0.x + h0.y * s0.y + h0.z * s0.z + h0.w * s0.w
               + h1v.x * s1.x + h1v.y * s1.y + h1v.z * s1.z + h1v.w * s1.w;
    g_ad1[idx] = h0.x * d0.x + h0.y * d0.y + h0.z * d0.z + h0.w * d0.w
               + h1v.x * d1.x + h1v.y * d1.y + h1v.z * d1.z + h1v.w * d1.w;
}

// =============================================================================
// CSR edge pass layer1: warp per dst, 4 edge-slots x 8 heads, 2x unrolled
// (edges e and e+4 per iteration -> per-lane MLP~4). No atomics.
// =============================================================================
__global__ __launch_bounds__(256) void k_agg1_csr() {
    int gw = (blockIdx.x * 256 + threadIdx.x) >> 5;   // dst node
    if (gw >= N_NODES) return;
    const int d    = gw;
    const int lane = threadIdx.x & 31;
    const int es   = lane >> 3;                        // edge slot 0..3
    const int l    = lane & 7;                         // head
    const int e0 = g_start[d], e1 = g_start[d + 1];

    const float ad = g_ad1[d * H1 + l];
    float acc[8] = {};
    float den = 0.f;

    int e = e0 + es;
    while (e < e1) {
        int sa = g_csr[e];
        int eb = e + 4;
        int sb = (eb < e1) ? g_csr[eb] : -1;
        // issue all independent loads up front
        float asa = g_as1[sa * H1 + l];
        float4 rawa = *(const float4*)&g_h1h[(size_t)sa * 32 + l * 4];
        float asb = 0.f; float4 rawb = make_float4(0.f, 0.f, 0.f, 0.f);
        if (sb >= 0) {
            asb = g_as1[sb * H1 + l];
            rawb = *(const float4*)&g_h1h[(size_t)sb * 32 + l * 4];
        }
        {
            float w = __expf(lrelu(asa + ad));
            __half2 p0 = *(__half2*)&rawa.x, p1 = *(__half2*)&rawa.y;
            __half2 p2 = *(__half2*)&rawa.z, p3 = *(__half2*)&rawa.w;
            float2 f0 = __half22float2(p0), f1 = __half22float2(p1);
            float2 f2 = __half22float2(p2), f3 = __half22float2(p3);
            acc[0] += w * f0.x; acc[1] += w * f0.y;
            acc[2] += w * f1.x; acc[3] += w * f1.y;
            acc[4] += w * f2.x; acc[5] += w * f2.y;
            acc[6] += w * f3.x; acc[7] += w * f3.y;
            den += w;
        }
        if (sb >= 0) {
            float w = __expf(lrelu(asb + ad));
            __half2 p0 = *(__half2*)&rawb.x, p1 = *(__half2*)&rawb.y;
            __half2 p2 = *(__half2*)&rawb.z, p3 = *(__half2*)&rawb.w;
            float2 f0 = __half22float2(p0), f1 = __half22float2(p1);
            float2 f2 = __half22float2(p2), f3 = __half22float2(p3);
            acc[0] += w * f0.x; acc[1] += w * f0.y;
            acc[2] += w * f1.x; acc[3] += w * f1.y;
            acc[4] += w * f2.x; acc[5] += w * f2.y;
            acc[6] += w * f3.x; acc[7] += w * f3.y;
            den += w;
        }
        e += 8;
    }
    __syncwarp();
#pragma unroll
    for (int off = 8; off <= 16; off <<= 1) {
#pragma unroll
        for (int k = 0; k < 8; k++) acc[k] += __shfl_xor_sync(0xffffffffu, acc[k], off);
        den += __shfl_xor_sync(0xffffffffu, den, off);
    }
    if (es == 0) {
        float* op = &g_out1[(size_t)d * D1 + l * C1];
        *(float4*)op       = make_float4(acc[0], acc[1], acc[2], acc[3]);
        *(float4*)(op + 4) = make_float4(acc[4], acc[5], acc[6], acc[7]);
        g_den1[d * H1 + l] = den;
    }
}

// =============================================================================
// layer2 prep (register-blocked tiled GEMM):
//   v = relu(out1/den1 + b1);  h2 = v @ W2 -> fp16 [N,48];  as2/ad2 fp32.
// =============================================================================
#define L2BM 128
__global__ __launch_bounds__(256) void k_l2prep(const float* __restrict__ b1,
                                                const float* __restrict__ W2,
                                                const float* __restrict__ att_src2,
                                                const float* __restrict__ att_dst2) {
    __shared__ float As[D1][L2BM + 4];
    __shared__ float Bs[D1][C2];
    __shared__ float b1s[D1];
    __shared__ float s2s[C2];
    __shared__ float d2s[C2];

    const int tid = threadIdx.x;
    const int row0 = blockIdx.x * L2BM;

    for (int i = tid; i < D1 * C2; i += 256) Bs[i / C2][i % C2] = W2[i];
    if (tid < D1) b1s[tid] = b1[tid];
    if (tid >= 64 && tid < 64 + C2) s2s[tid - 64] = att_src2[tid - 64];
    if (tid >= 128 && tid < 128 + C2) d2s[tid - 128] = att_dst2[tid - 128];
    __syncthreads();

#pragma unroll
    for (int i = 0; i < 8; i++) {
        int fid = tid + i * 256;
        int r = fid >> 4;
        int c4 = fid & 15;
        int gr = row0 + r;
        if (gr >= N_NODES) gr = N_NODES - 1;
        float q = 1.f / (g_den1[gr * H1 + (c4 >> 1)] + 1e-16f);
        float4 v = *(const float4*)&g_out1[(size_t)gr * D1 + c4 * 4];
        float e0 = v.x * q + b1s[c4 * 4 + 0];
        float e1 = v.y * q + b1s[c4 * 4 + 1];
        float e2 = v.z * q + b1s[c4 * 4 + 2];
        float e3 = v.w * q + b1s[c4 * 4 + 3];
        As[c4 * 4 + 0][r] = e0 > 0.f ? e0 : 0.f;
        As[c4 * 4 + 1][r] = e1 > 0.f ? e1 : 0.f;
        As[c4 * 4 + 2][r] = e2 > 0.f ? e2 : 0.f;
        As[c4 * 4 + 3][r] = e3 > 0.f ? e3 : 0.f;
    }
    __syncthreads();

    const int ty = tid >> 3;
    const int tx = tid & 7;
    float acc[4][5] = {};

#pragma unroll
    for (int k = 0; k < D1; k++) {
        float4 av = *(const float4*)&As[k][ty * 4];
        float a[4] = {av.x, av.y, av.z, av.w};
        float b[5];
#pragma unroll
        for (int j = 0; j < 5; j++) b[j] = Bs[k][tx * 5 + j];
#pragma unroll
        for (int i = 0; i < 4; i++)
#pragma unroll
            for (int j = 0; j < 5; j++) acc[i][j] += a[i] * b[j];
    }

#pragma unroll
    for (int i = 0; i < 4; i++) {
        int gr = row0 + ty * 4 + i;
        float ps = 0.f, pd = 0.f;
#pragma unroll
        for (int j = 0; j < 5; j++) {
            ps += acc[i][j] * s2s[tx * 5 + j];
            pd += acc[i][j] * d2s[tx * 5 + j];
        }
#pragma unroll
        for (int o = 4; o; o >>= 1) {
            ps += __shfl_xor_sync(0xffffffffu, ps, o);
            pd += __shfl_xor_sync(0xffffffffu, pd, o);
        }
        if (gr < N_NODES) {
#pragma unroll
            for (int j = 0; j < 5; j++)
                g_h2h[(size_t)gr * C2P + tx * 5 + j] = __float2half_rn(acc[i][j]);
            if (tx == 0) { g_as2[gr] = ps; g_ad2[gr] = pd; }
        }
    }
}

// =============================================================================
// CSR edge pass layer2: warp per dst, lanes l<5 carry 8 halfs (80B row),
// 2x unrolled. No atomics.
// =============================================================================
__global__ __launch_bounds__(256) void k_agg2_csr(float* __restrict__ out) {
    int gw = (blockIdx.x * 256 + threadIdx.x) >> 5;
    if (gw >= N_NODES) return;
    const int d    = gw;
    const int lane = threadIdx.x & 31;
    const int es   = lane >> 3;
    const int l    = lane & 7;
    const int e0 = g_start[d], e1 = g_start[d + 1];

    const float ad = g_ad2[d];
    float acc[8] = {};
    float den = 0.f;

    int e = e0 + es;
    while (e < e1) {
        int sa = g_csr[e];
        int eb = e + 4;
        int sb = (eb < e1) ? g_csr[eb] : -1;
        float asa = g_as2[sa];
        float4 rawa = make_float4(0.f, 0.f, 0.f, 0.f);
        if (l < 5) rawa = *(const float4*)&g_h2h[(size_t)sa * C2P + l * 8];
        float asb = 0.f; float4 rawb = make_float4(0.f, 0.f, 0.f, 0.f);
        if (sb >= 0) {
            asb = g_as2[sb];
            if (l < 5) rawb = *(const float4*)&g_h2h[(size_t)sb * C2P + l * 8];
        }
        {
            float w = __expf(lrelu(asa + ad));
            __half2 p0 = *(__half2*)&rawa.x, p1 = *(__half2*)&rawa.y;
            __half2 p2 = *(__half2*)&rawa.z, p3 = *(__half2*)&rawa.w;
            float2 f0 = __half22float2(p0), f1 = __half22float2(p1);
            float2 f2 = __half22float2(p2), f3 = __half22float2(p3);
            acc[0] += w * f0.x; acc[1] += w * f0.y;
            acc[2] += w * f1.x; acc[3] += w * f1.y;
            acc[4] += w * f2.x; acc[5] += w * f2.y;
            acc[6] += w * f3.x; acc[7] += w * f3.y;
            den += w;
        }
        if (sb >= 0) {
            float w = __expf(lrelu(asb + ad));
            __half2 p0 = *(__half2*)&rawb.x, p1 = *(__half2*)&rawb.y;
            __half2 p2 = *(__half2*)&rawb.z, p3 = *(__half2*)&rawb.w;
            float2 f0 = __half22float2(p0), f1 = __half22float2(p1);
            float2 f2 = __half22float2(p2), f3 = __half22float2(p3);
            acc[0] += w * f0.x; acc[1] += w * f0.y;
            acc[2] += w * f1.x; acc[3] += w * f1.y;
            acc[4] += w * f2.x; acc[5] += w * f2.y;
            acc[6] += w * f3.x; acc[7] += w * f3.y;
            den += w;
        }
        e += 8;
    }
    __syncwarp();
#pragma unroll
    for (int off = 8; off <= 16; off <<= 1) {
#pragma unroll
        for (int k = 0; k < 8; k++) acc[k] += __shfl_xor_sync(0xffffffffu, acc[k], off);
        den += __shfl_xor_sync(0xffffffffu, den, off);
    }
    if (es == 0) {
        if (l < 5) {
            float* op = &out[(size_t)d * C2 + l * 8];
            *(float4*)op       = make_float4(acc[0], acc[1], acc[2], acc[3]);
            *(float4*)(op + 4) = make_float4(acc[4], acc[5], acc[6], acc[7]);
        }
        if (l == 7) g_den2[d] = den;
    }
}

// =============================================================================
// finalize: out = log_softmax(out/den2 + b2) per node (warp/node)
// =============================================================================
__global__ __launch_bounds__(256) void k_final(float* __restrict__ out,
                                               const float* __restrict__ b2) {
    const int w = threadIdx.x >> 5;
    const int lane = threadIdx.x & 31;
    const int n = blockIdx.x * 8 + w;
    if (n >= N_NODES) return;
    float* row = &out[(size_t)n * C2];
    float q = 1.f / (g_den2[n] + 1e-16f);
    float x0 = row[lane] * q + b2[lane];
    float x1 = (lane < 8) ? row[32 + lane] * q + b2[32 + lane] : -1e30f;
    float m = fmaxf(x0, x1);
#pragma unroll
    for (int o = 16; o; o >>= 1) m = fmaxf(m, __shfl_xor_sync(0xffffffffu, m, o));
    float s = expf(x0 - m) + ((lane < 8) ? expf(x1 - m) : 0.f);
#pragma unroll
    for (int o = 16; o; o >>= 1) s += __shfl_xor_sync(0xffffffffu, s, o);
    float l = m + logf(s);
    row[lane] = x0 - l;
    if (lane < 8) row[32 + lane] = x1 - l;
}

// =============================================================================
extern "C" void kernel_launch(void* const* d_in, const int* in_sizes, int n_in,
                              void* d_out, int out_size) {
    const float* x        = (const float*)d_in[0];
    const int*   ei       = (const int*)d_in[1];
    const float* W1       = (const float*)d_in[2];
    const float* att_src1 = (const float*)d_in[3];
    const float* att_dst1 = (const float*)d_in[4];
    const float* b1       = (const float*)d_in[5];
    const float* W2       = (const float*)d_in[6];
    const float* att_src2 = (const float*)d_in[7];
    const float* att_dst2 = (const float*)d_in[8];
    const float* b2       = (const float*)d_in[9];
    float*       out      = (float*)d_out;
    (void)in_sizes; (void)n_in; (void)out_size;

    void *p_cnt;
    cudaGetSymbolAddress(&p_cnt, g_cnt);
    cudaMemsetAsync(p_cnt, 0, (size_t)N_NODES * sizeof(int));

    const int TB = 256;
    // CSR build
    k_count<<<(EN_TOT + TB - 1) / TB, TB>>>(ei);
    k_scanA<<<NBLK, 1024>>>();
    k_scanB<<<1, 128>>>();
    k_scanC<<<NBLK, 1024>>>();
    k_fill<<<(EN_TOT + TB - 1) / TB, TB>>>(ei);
    // GAT pipeline
    k_gemm1<<<(N_NODES + BM - 1) / BM, TB>>>(x, W1);
    k_att1<<<(N_NODES * H1 + TB - 1) / TB, TB>>>(att_src1, att_dst1);
    k_agg1_csr<<<(N_NODES * 32 + TB - 1) / TB, TB>>>();
    k_l2prep<<<(N_NODES + L2BM - 1) / L2BM, TB>>>(b1, W2, att_src2, att_dst2);
    k_agg2_csr<<<(N_NODES * 32 + TB - 1) / TB, TB>>>(out);
    k_final<<<(N_NODES + 7) / 8, TB>>>(out, b2);
}

// round 16
// speedup vs baseline: 1.3881x; 1.0215x over previous
#include <cuda_runtime.h>
#include <cuda_fp16.h>
#include <cstdint>

#define N_NODES 100000
#define N_EDGES 1600000
#define EN_TOT  (N_EDGES + N_NODES)   // edges + self loops
#define F_IN    512
#define H1      8
#define C1      8
#define D1      64                    // H1*C1
#define C2      40
#define C2P     48                    // padded h2 fp16 row (96B, 16B-aligned float4s)
#define NBLK    ((N_NODES + 1023) / 1024)   // 98 scan blocks

// ---------------- scratch (static device allocations; allowed) ----------------
__device__ float   g_h1 [N_NODES * D1];       // layer1 linear output fp32 [N,64]
__device__ __half2 g_h1h[N_NODES * (D1 / 2)]; // fp16 mirror for edge gather
__device__ float g_as1[N_NODES * H1];
__device__ float g_ad1[N_NODES * H1];
__device__ float g_den1[N_NODES * H1];
__device__ float g_out1[N_NODES * D1];
__device__ __half g_h2h[N_NODES * C2P];
__device__ float g_as2[N_NODES];
__device__ float g_ad2[N_NODES];
__device__ float g_den2[N_NODES];
// CSR scratch
__device__ int g_cnt [N_NODES];
__device__ int g_cnt2[N_NODES];
__device__ int g_start[N_NODES + 1];
__device__ int g_blksum[NBLK];
__device__ int g_blkoff[NBLK];
__device__ int g_csr[EN_TOT];

__device__ __forceinline__ float lrelu(float e) { return e > 0.f ? e : 0.2f * e; }

__device__ __forceinline__ float to_tf32(float x) {
    uint32_t r;
    asm("cvt.rna.tf32.f32 %0, %1;" : "=r"(r) : "f"(x));
    return __uint_as_float(r);
}

// edge_index is int32 on device.
__device__ __forceinline__ void edge_sd(const int* __restrict__ ei, int i, int& s, int& d) {
    if (i < N_EDGES) { s = __ldg(&ei[i]); d = __ldg(&ei[N_EDGES + i]); }
    else             { s = d = i - N_EDGES; }
}

// =============================================================================
// CSR build: count -> scan (3 kernels) -> fill
// =============================================================================
__global__ void k_count(const int* __restrict__ ei) {
    int i = blockIdx.x * blockDim.x + threadIdx.x;
    if (i >= EN_TOT) return;
    int d = (i < N_EDGES) ? __ldg(&ei[N_EDGES + i]) : i - N_EDGES;   // dst only
    atomicAdd(&g_cnt[d], 1);
}

__global__ __launch_bounds__(1024) void k_scanA() {
    __shared__ int sm[1024];
    int t = blockIdx.x * 1024 + threadIdx.x;
    int v = (t < N_NODES) ? g_cnt[t] : 0;
    sm[threadIdx.x] = v;
    __syncthreads();
#pragma unroll
    for (int off = 1; off < 1024; off <<= 1) {
        int x = (threadIdx.x >= off) ? sm[threadIdx.x - off] : 0;
        __syncthreads();
        sm[threadIdx.x] += x;
        __syncthreads();
    }
    if (t < N_NODES) g_start[t] = sm[threadIdx.x] - v;       // exclusive within block
    if (threadIdx.x == 1023) g_blksum[blockIdx.x] = sm[1023];
}

__global__ void k_scanB() {          // 1 block, 128 threads, NBLK<=128
    __shared__ int sm[128];
    int t = threadIdx.x;
    int v = (t < NBLK) ? g_blksum[t] : 0;
    sm[t] = v;
    __syncthreads();
#pragma unroll
    for (int off = 1; off < 128; off <<= 1) {
        int x = (t >= off) ? sm[t - off] : 0;
        __syncthreads();
        sm[t] += x;
        __syncthreads();
    }
    if (t < NBLK) g_blkoff[t] = sm[t] - v;
}

__global__ __launch_bounds__(1024) void k_scanC() {
    int t = blockIdx.x * 1024 + threadIdx.x;
    if (t < N_NODES) {
        g_start[t] += g_blkoff[blockIdx.x];
        g_cnt2[t] = 0;                    // fold cursor init here (no memset)
    }
    if (t == 0) g_start[N_NODES] = EN_TOT;
}

__global__ void k_fill(const int* __restrict__ ei) {
    int i = blockIdx.x * blockDim.x + threadIdx.x;
    if (i >= EN_TOT) return;
    int s, d; edge_sd(ei, i, s, d);
    int pos = atomicAdd(&g_cnt2[d], 1);
    g_csr[g_start[d] + pos] = s;
}

// =============================================================================
// GEMM1 (tf32 tensor-core): h1 = x @ W1 -> stored fp32 AND fp16 mirror.
// =============================================================================
#define BM 128
#define BN 64
#define BK 32
__global__ __launch_bounds__(256) void k_gemm1(const float* __restrict__ X,
                                               const float* __restrict__ W) {
    __shared__ float As[BK][BM + 8];
    __shared__ float Bs[BK][BN + 8];

    const int tid  = threadIdx.x;
    const int wid  = tid >> 5;
    const int lane = tid & 31;
    const int wm   = wid & 3;
    const int wn   = wid >> 2;
    const int lr   = lane >> 2;
    const int lc   = lane & 3;
    const int row0 = blockIdx.x * BM;

    float acc[2][4][4] = {};

    for (int k0 = 0; k0 < F_IN; k0 += BK) {
#pragma unroll
        for (int i = 0; i < 4; i++) {
            int fid = tid + i * 256;
            int r = fid >> 3;
            int c4 = fid & 7;
            int gr = row0 + r;
            if (gr >= N_NODES) gr = N_NODES - 1;
            float4 v = *(const float4*)&X[(size_t)gr * F_IN + k0 + c4 * 4];
            As[c4 * 4 + 0][r] = to_tf32(v.x);
            As[c4 * 4 + 1][r] = to_tf32(v.y);
            As[c4 * 4 + 2][r] = to_tf32(v.z);
            As[c4 * 4 + 3][r] = to_tf32(v.w);
        }
#pragma unroll
        for (int i = 0; i < 2; i++) {
            int fid = tid + i * 256;
            int r = fid >> 4;
            int c4 = fid & 15;
            float4 v = *(const float4*)&W[(k0 + r) * BN + c4 * 4];
            float4 t = make_float4(to_tf32(v.x), to_tf32(v.y), to_tf32(v.z), to_tf32(v.w));
            *(float4*)&Bs[r][c4 * 4] = t;
        }
        __syncthreads();

#pragma unroll
        for (int kk = 0; kk < BK; kk += 8) {
            uint32_t a[2][4], b[4][2];
#pragma unroll
            for (int mt = 0; mt < 2; mt++) {
                int m0 = wm * 32 + mt * 16;
                a[mt][0] = __float_as_uint(As[kk + lc    ][m0 + lr    ]);
                a[mt][1] = __float_as_uint(As[kk + lc    ][m0 + lr + 8]);
                a[mt][2] = __float_as_uint(As[kk + lc + 4][m0 + lr    ]);
                a[mt][3] = __float_as_uint(As[kk + lc + 4][m0 + lr + 8]);
            }
#pragma unroll
            for (int nt = 0; nt < 4; nt++) {
                int n0 = wn * 32 + nt * 8;
                b[nt][0] = __float_as_uint(Bs[kk + lc    ][n0 + lr]);
                b[nt][1] = __float_as_uint(Bs[kk + lc + 4][n0 + lr]);
            }
#pragma unroll
            for (int mt = 0; mt < 2; mt++)
#pragma unroll
                for (int nt = 0; nt < 4; nt++) {
                    asm volatile(
                        "mma.sync.aligned.m16n8k8.row.col.f32.tf32.tf32.f32 "
                        "{%0,%1,%2,%3}, {%4,%5,%6,%7}, {%8,%9}, {%0,%1,%2,%3};"
                        : "+f"(acc[mt][nt][0]), "+f"(acc[mt][nt][1]),
                          "+f"(acc[mt][nt][2]), "+f"(acc[mt][nt][3])
                        : "r"(a[mt][0]), "r"(a[mt][1]), "r"(a[mt][2]), "r"(a[mt][3]),
                          "r"(b[nt][0]), "r"(b[nt][1]));
                }
        }
        __syncthreads();
    }

#pragma unroll
    for (int mt = 0; mt < 2; mt++) {
#pragma unroll
        for (int nt = 0; nt < 4; nt++) {
            int r0 = row0 + wm * 32 + mt * 16 + lr;
            int c0 = wn * 32 + nt * 8 + 2 * lc;
            if (r0 < N_NODES) {
                *(float2*)&g_h1[(size_t)r0 * D1 + c0] =
                    make_float2(acc[mt][nt][0], acc[mt][nt][1]);
                g_h1h[(size_t)r0 * 32 + (c0 >> 1)] =
                    __floats2half2_rn(acc[mt][nt][0], acc[mt][nt][1]);
            }
            if (r0 + 8 < N_NODES) {
                *(float2*)&g_h1[(size_t)(r0 + 8) * D1 + c0] =
                    make_float2(acc[mt][nt][2], acc[mt][nt][3]);
                g_h1h[(size_t)(r0 + 8) * 32 + (c0 >> 1)] =
                    __floats2half2_rn(acc[mt][nt][2], acc[mt][nt][3]);
            }
        }
    }
}

// =============================================================================
// att1: per (node,head) attention scalars (fp32 h1 — full precision)
// =============================================================================
__global__ void k_att1(const float* __restrict__ att_src, const float* __restrict__ att_dst) {
    int idx = blockIdx.x * blockDim.x + threadIdx.x;
    if (idx >= N_NODES * H1) return;
    int h = idx & 7, n = idx >> 3;
    const float4* hp = (const float4*)&g_h1[(size_t)n * D1 + h * C1];
    float4 h0 = hp[0], h1v = hp[1];
    const float4* sp = (const float4*)&att_src[h * C1];
    const float4* dp = (const float4*)&att_dst[h * C1];
    float4 s0 = sp[0], s1 = sp[1], d0 = dp[0], d1 = dp[1];
    g_as1[idx] = h0.x * s0.x + h0.y * s0.y + h0.z * s0.z + h0.w * s0.w
               + h1v.x * s1.x + h1v.y * s1.y + h1v.z * s1.z + h1v.w * s1.w;
    g_ad1[idx] = h0.x * d0.x + h0.y * d0.y + h0.z * d0.z + h0.w * d0.w
               + h1v.x * d1.x + h1v.y * d1.y + h1v.z * d1.z + h1v.w * d1.w;
}

// =============================================================================
// CSR edge pass layer1: warp per dst, 4 edge-slots x 8 heads, 2x unrolled.
// No atomics.
// =============================================================================
__global__ __launch_bounds__(256) void k_agg1_csr() {
    int gw = (blockIdx.x * 256 + threadIdx.x) >> 5;   // dst node
    if (gw >= N_NODES) return;
    const int d    = gw;
    const int lane = threadIdx.x & 31;
    const int es   = lane >> 3;                        // edge slot 0..3
    const int l    = lane & 7;                         // head
    const int e0 = g_start[d], e1 = g_start[d + 1];

    const float ad = g_ad1[d * H1 + l];
    float acc[8] = {};
    float den = 0.f;

    int e = e0 + es;
    while (e < e1) {
        int sa = g_csr[e];
        int eb = e + 4;
        int sb = (eb < e1) ? g_csr[eb] : -1;
        float asa = g_as1[sa * H1 + l];
        float4 rawa = *(const float4*)&g_h1h[(size_t)sa * 32 + l * 4];
        float asb = 0.f; float4 rawb = make_float4(0.f, 0.f, 0.f, 0.f);
        if (sb >= 0) {
            asb = g_as1[sb * H1 + l];
            rawb = *(const float4*)&g_h1h[(size_t)sb * 32 + l * 4];
        }
        {
            float w = __expf(lrelu(asa + ad));
            __half2 p0 = *(__half2*)&rawa.x, p1 = *(__half2*)&rawa.y;
            __half2 p2 = *(__half2*)&rawa.z, p3 = *(__half2*)&rawa.w;
            float2 f0 = __half22float2(p0), f1 = __half22float2(p1);
            float2 f2 = __half22float2(p2), f3 = __half22float2(p3);
            acc[0] += w * f0.x; acc[1] += w * f0.y;
            acc[2] += w * f1.x; acc[3] += w * f1.y;
            acc[4] += w * f2.x; acc[5] += w * f2.y;
            acc[6] += w * f3.x; acc[7] += w * f3.y;
            den += w;
        }
        if (sb >= 0) {
            float w = __expf(lrelu(asb + ad));
            __half2 p0 = *(__half2*)&rawb.x, p1 = *(__half2*)&rawb.y;
            __half2 p2 = *(__half2*)&rawb.z, p3 = *(__half2*)&rawb.w;
            float2 f0 = __half22float2(p0), f1 = __half22float2(p1);
            float2 f2 = __half22float2(p2), f3 = __half22float2(p3);
            acc[0] += w * f0.x; acc[1] += w * f0.y;
            acc[2] += w * f1.x; acc[3] += w * f1.y;
            acc[4] += w * f2.x; acc[5] += w * f2.y;
            acc[6] += w * f3.x; acc[7] += w * f3.y;
            den += w;
        }
        e += 8;
    }
    __syncwarp();
#pragma unroll
    for (int off = 8; off <= 16; off <<= 1) {
#pragma unroll
        for (int k = 0; k < 8; k++) acc[k] += __shfl_xor_sync(0xffffffffu, acc[k], off);
        den += __shfl_xor_sync(0xffffffffu, den, off);
    }
    if (es == 0) {
        float* op = &g_out1[(size_t)d * D1 + l * C1];
        *(float4*)op       = make_float4(acc[0], acc[1], acc[2], acc[3]);
        *(float4*)(op + 4) = make_float4(acc[4], acc[5], acc[6], acc[7]);
        g_den1[d * H1 + l] = den;
    }
}

// =============================================================================
// layer2 prep — tf32 tensor-core version:
//   v = relu(out1/den1 + b1) (tf32, in A-tile fill);  h2 = v @ W2 -> fp16;
//   as2/ad2 = h2 . att2 (fp32 epilogue + quad shuffle reduce).
// Block: 128 rows x 40 cols, K=64 whole.  8 warps, each 16 rows x 40 cols
// = 5 n-tiles of m16n8k8, 8 k-steps.
// =============================================================================
#define L2BM 128
__global__ __launch_bounds__(256) void k_l2prep(const float* __restrict__ b1,
                                                const float* __restrict__ W2,
                                                const float* __restrict__ att_src2,
                                                const float* __restrict__ att_dst2) {
    __shared__ float As[D1][L2BM + 8];   // [k][m] tf32, row stride 136
    __shared__ float Bs[D1][C2 + 8];     // [k][n] tf32, row stride 48
    __shared__ float b1s[D1];
    __shared__ float s2s[C2];
    __shared__ float d2s[C2];

    const int tid  = threadIdx.x;
    const int wid  = tid >> 5;
    const int lane = tid & 31;
    const int lr   = lane >> 2;          // 0..7
    const int lc   = lane & 3;           // 0..3
    const int row0 = blockIdx.x * L2BM;
    const int m0   = wid * 16;           // warp's 16-row slab

    for (int i = tid; i < D1 * C2; i += 256) Bs[i / C2][i % C2] = to_tf32(W2[i]);
    if (tid < D1) b1s[tid] = b1[tid];
    if (tid >= 64 && tid < 64 + C2) s2s[tid - 64] = att_src2[tid - 64];
    if (tid >= 128 && tid < 128 + C2) d2s[tid - 128] = att_dst2[tid - 128];
    __syncthreads();                     // b1s ready before A fill

    // A tile: 128 rows x 16 float4, 8 per thread; normalize+bias+relu+tf32.
#pragma unroll
    for (int i = 0; i < 8; i++) {
        int fid = tid + i * 256;
        int r = fid >> 4;
        int c4 = fid & 15;
        int gr = row0 + r;
        if (gr >= N_NODES) gr = N_NODES - 1;
        float q = 1.f / (g_den1[gr * H1 + (c4 >> 1)] + 1e-16f);
        float4 v = *(const float4*)&g_out1[(size_t)gr * D1 + c4 * 4];
        float e0 = v.x * q + b1s[c4 * 4 + 0];
        float e1 = v.y * q + b1s[c4 * 4 + 1];
        float e2 = v.z * q + b1s[c4 * 4 + 2];
        float e3 = v.w * q + b1s[c4 * 4 + 3];
        As[c4 * 4 + 0][r] = to_tf32(e0 > 0.f ? e0 : 0.f);
        As[c4 * 4 + 1][r] = to_tf32(e1 > 0.f ? e1 : 0.f);
        As[c4 * 4 + 2][r] = to_tf32(e2 > 0.f ? e2 : 0.f);
        As[c4 * 4 + 3][r] = to_tf32(e3 > 0.f ? e3 : 0.f);
    }
    __syncthreads();

    float acc[5][4] = {};
#pragma unroll
    for (int kk = 0; kk < D1; kk += 8) {
        uint32_t a[4], b[5][2];
        a[0] = __float_as_uint(As[kk + lc    ][m0 + lr    ]);
        a[1] = __float_as_uint(As[kk + lc    ][m0 + lr + 8]);
        a[2] = __float_as_uint(As[kk + lc + 4][m0 + lr    ]);
        a[3] = __float_as_uint(As[kk + lc + 4][m0 + lr + 8]);
#pragma unroll
        for (int nt = 0; nt < 5; nt++) {
            b[nt][0] = __float_as_uint(Bs[kk + lc    ][nt * 8 + lr]);
            b[nt][1] = __float_as_uint(Bs[kk + lc + 4][nt * 8 + lr]);
        }
#pragma unroll
        for (int nt = 0; nt < 5; nt++) {
            asm volatile(
                "mma.sync.aligned.m16n8k8.row.col.f32.tf32.tf32.f32 "
                "{%0,%1,%2,%3}, {%4,%5,%6,%7}, {%8,%9}, {%0,%1,%2,%3};"
                : "+f"(acc[nt][0]), "+f"(acc[nt][1]),
                  "+f"(acc[nt][2]), "+f"(acc[nt][3])
                : "r"(a[0]), "r"(a[1]), "r"(a[2]), "r"(a[3]),
                  "r"(b[nt][0]), "r"(b[nt][1]));
        }
    }

    // Epilogue: h2 fp16 stores + att2 dots (quad reduce over lc).
    int r0 = row0 + m0 + lr;
    int r1 = r0 + 8;
    float psA = 0.f, pdA = 0.f, psB = 0.f, pdB = 0.f;
#pragma unroll
    for (int nt = 0; nt < 5; nt++) {
        int c0 = nt * 8 + 2 * lc;
        psA += acc[nt][0] * s2s[c0] + acc[nt][1] * s2s[c0 + 1];
        pdA += acc[nt][0] * d2s[c0] + acc[nt][1] * d2s[c0 + 1];
        psB += acc[nt][2] * s2s[c0] + acc[nt][3] * s2s[c0 + 1];
        pdB += acc[nt][2] * d2s[c0] + acc[nt][3] * d2s[c0 + 1];
    }
#pragma unroll
    for (int o = 1; o <= 2; o <<= 1) {
        psA += __shfl_xor_sync(0xffffffffu, psA, o);
        pdA += __shfl_xor_sync(0xffffffffu, pdA, o);
        psB += __shfl_xor_sync(0xffffffffu, psB, o);
        pdB += __shfl_xor_sync(0xffffffffu, pdB, o);
    }
    if (r0 < N_NODES) {
#pragma unroll
        for (int nt = 0; nt < 5; nt++)
            *(__half2*)&g_h2h[(size_t)r0 * C2P + nt * 8 + 2 * lc] =
                __floats2half2_rn(acc[nt][0], acc[nt][1]);
        if (lc == 0) { g_as2[r0] = psA; g_ad2[r0] = pdA; }
    }
    if (r1 < N_NODES) {
#pragma unroll
        for (int nt = 0; nt < 5; nt++)
            *(__half2*)&g_h2h[(size_t)r1 * C2P + nt * 8 + 2 * lc] =
                __floats2half2_rn(acc[nt][2], acc[nt][3]);
        if (lc == 0) { g_as2[r1] = psB; g_ad2[r1] = pdB; }
    }
}

// =============================================================================
// CSR edge pass layer2: warp per dst, lanes l<5 carry 8 halfs (80B row),
// 2x unrolled. No atomics.
// =============================================================================
__global__ __launch_bounds__(256) void k_agg2_csr(float* __restrict__ out) {
    int gw = (blockIdx.x * 256 + threadIdx.x) >> 5;
    if (gw >= N_NODES) return;
    const int d    = gw;
    const int lane = threadIdx.x & 31;
    const int es   = lane >> 3;
    const int l    = lane & 7;
    const int e0 = g_start[d], e1 = g_start[d + 1];

    const float ad = g_ad2[d];
    float acc[8] = {};
    float den = 0.f;

    int e = e0 + es;
    while (e < e1) {
        int sa = g_csr[e];
        int eb = e + 4;
        int sb = (eb < e1) ? g_csr[eb] : -1;
        float asa = g_as2[sa];
        float4 rawa = make_float4(0.f, 0.f, 0.f, 0.f);
        if (l < 5) rawa = *(const float4*)&g_h2h[(size_t)sa * C2P + l * 8];
        float asb = 0.f; float4 rawb = make_float4(0.f, 0.f, 0.f, 0.f);
        if (sb >= 0) {
            asb = g_as2[sb];
            if (l < 5) rawb = *(const float4*)&g_h2h[(size_t)sb * C2P + l * 8];
        }
        {
            float w = __expf(lrelu(asa + ad));
            __half2 p0 = *(__half2*)&rawa.x, p1 = *(__half2*)&rawa.y;
            __half2 p2 = *(__half2*)&rawa.z, p3 = *(__half2*)&rawa.w;
            float2 f0 = __half22float2(p0), f1 = __half22float2(p1);
            float2 f2 = __half22float2(p2), f3 = __half22float2(p3);
            acc[0] += w * f0.x; acc[1] += w * f0.y;
            acc[2] += w * f1.x; acc[3] += w * f1.y;
            acc[4] += w * f2.x; acc[5] += w * f2.y;
            acc[6] += w * f3.x; acc[7] += w * f3.y;
            den += w;
        }
        if (sb >= 0) {
            float w = __expf(lrelu(asb + ad));
            __half2 p0 = *(__half2*)&rawb.x, p1 = *(__half2*)&rawb.y;
            __half2 p2 = *(__half2*)&rawb.z, p3 = *(__half2*)&rawb.w;
            float2 f0 = __half22float2(p0), f1 = __half22float2(p1);
            float2 f2 = __half22float2(p2), f3 = __half22float2(p3);
            acc[0] += w * f0.x; acc[1] += w * f0.y;
            acc[2] += w * f1.x; acc[3] += w * f1.y;
            acc[4] += w * f2.x; acc[5] += w * f2.y;
            acc[6] += w * f3.x; acc[7] += w * f3.y;
            den += w;
        }
        e += 8;
    }
    __syncwarp();
#pragma unroll
    for (int off = 8; off <= 16; off <<= 1) {
#pragma unroll
        for (int k = 0; k < 8; k++) acc[k] += __shfl_xor_sync(0xffffffffu, acc[k], off);
        den += __shfl_xor_sync(0xffffffffu, den, off);
    }
    if (es == 0) {
        if (l < 5) {
            float* op = &out[(size_t)d * C2 + l * 8];
            *(float4*)op       = make_float4(acc[0], acc[1], acc[2], acc[3]);
            *(float4*)(op + 4) = make_float4(acc[4], acc[5], acc[6], acc[7]);
        }
        if (l == 7) g_den2[d] = den;
    }
}

// =============================================================================
// finalize: out = log_softmax(out/den2 + b2) per node (warp/node)
// =============================================================================
__global__ __launch_bounds__(256) void k_final(float* __restrict__ out,
                                               const float* __restrict__ b2) {
    const int w = threadIdx.x >> 5;
    const int lane = threadIdx.x & 31;
    const int n = blockIdx.x * 8 + w;
    if (n >= N_NODES) return;
    float* row = &out[(size_t)n * C2];
    float q = 1.f / (g_den2[n] + 1e-16f);
    float x0 = row[lane] * q + b2[lane];
    float x1 = (lane < 8) ? row[32 + lane] * q + b2[32 + lane] : -1e30f;
    float m = fmaxf(x0, x1);
#pragma unroll
    for (int o = 16; o; o >>= 1) m = fmaxf(m, __shfl_xor_sync(0xffffffffu, m, o));
    float s = expf(x0 - m) + ((lane < 8) ? expf(x1 - m) : 0.f);
#pragma unroll
    for (int o = 16; o; o >>= 1) s += __shfl_xor_sync(0xffffffffu, s, o);
    float l = m + logf(s);
    row[lane] = x0 - l;
    if (lane < 8) row[32 + lane] = x1 - l;
}

// =============================================================================
extern "C" void kernel_launch(void* const* d_in, const int* in_sizes, int n_in,
                              void* d_out, int out_size) {
    const float* x        = (const float*)d_in[0];
    const int*   ei       = (const int*)d_in[1];
    const float* W1       = (const float*)d_in[2];
    const float* att_src1 = (const float*)d_in[3];
    const float* att_dst1 = (const float*)d_in[4];
    const float* b1       = (const float*)d_in[5];
    const float* W2       = (const float*)d_in[6];
    const float* att_src2 = (const float*)d_in[7];
    const float* att_dst2 = (const float*)d_in[8];
    const float* b2       = (const float*)d_in[9];
    float*       out      = (float*)d_out;
    (void)in_sizes; (void)n_in; (void)out_size;

    void *p_cnt;
    cudaGetSymbolAddress(&p_cnt, g_cnt);
    cudaMemsetAsync(p_cnt, 0, (size_t)N_NODES * sizeof(int));

    const int TB = 256;
    // CSR build
    k_count<<<(EN_TOT + TB - 1) / TB, TB>>>(ei);
    k_scanA<<<NBLK, 1024>>>();
    k_scanB<<<1, 128>>>();
    k_scanC<<<NBLK, 1024>>>();
    k_fill<<<(EN_TOT + TB - 1) / TB, TB>>>(ei);
    // GAT pipeline
    k_gemm1<<<(N_NODES + BM - 1) / BM, TB>>>(x, W1);
    k_att1<<<(N_NODES * H1 + TB - 1) / TB, TB>>>(att_src1, att_dst1);
    k_agg1_csr<<<(N_NODES * 32 + TB - 1) / TB, TB>>>();
    k_l2prep<<<(N_NODES + L2BM - 1) / L2BM, TB>>>(b1, W2, att_src2, att_dst2);
    k_agg2_csr<<<(N_NODES * 32 + TB - 1) / TB, TB>>>(out);
    k_final<<<(N_NODES + 7) / 8, TB>>>(out, b2);
}